// round 1
// baseline (speedup 1.0000x reference)
#include <cuda_runtime.h>

#define B_SZ  4096
#define IN_F  256
#define OUT_F 256
#define HYP   128

// Scratch for hidden activations (allocation-free rule: __device__ globals)
__device__ float g_hg[B_SZ * HYP];
__device__ float g_hb[B_SZ * HYP];

// ---------------------------------------------------------------------------
// Kernel 1: hg = relu(x@W1g + b1g), hb = relu(x@W1b + b1b)
// Block: 16 batch rows, 256 threads. tid = half*128 + h.
// Each thread computes 8 rows x 1 hidden unit for BOTH matrices.
// W loads coalesced (h contiguous across lanes), x rows broadcast from smem.
// ---------------------------------------------------------------------------
__global__ __launch_bounds__(256) void hidden_kernel(
    const float* __restrict__ x,
    const float* __restrict__ W1g, const float* __restrict__ b1g,
    const float* __restrict__ W1b, const float* __restrict__ b1b)
{
    __shared__ __align__(16) float xs[16 * IN_F];
    const int b0   = blockIdx.x * 16;
    const int tid  = threadIdx.x;
    const int h    = tid & (HYP - 1);
    const int half = tid >> 7;  // 0 or 1 -> rows [half*8, half*8+8)

    for (int idx = tid; idx < 16 * IN_F / 4; idx += 256)
        ((float4*)xs)[idx] = ((const float4*)(x + (size_t)b0 * IN_F))[idx];
    __syncthreads();

    float accg[8], accb[8];
#pragma unroll
    for (int r = 0; r < 8; r++) { accg[r] = 0.f; accb[r] = 0.f; }

    for (int i = 0; i < IN_F; i++) {
        float wg = W1g[i * HYP + h];
        float wb = W1b[i * HYP + h];
#pragma unroll
        for (int r = 0; r < 8; r++) {
            float xv = xs[(half * 8 + r) * IN_F + i];
            accg[r] = fmaf(xv, wg, accg[r]);
            accb[r] = fmaf(xv, wb, accb[r]);
        }
    }
    float bg = b1g[h], bb = b1b[h];
#pragma unroll
    for (int r = 0; r < 8; r++) {
        int row = b0 + half * 8 + r;
        g_hg[row * HYP + h] = fmaxf(accg[r] + bg, 0.f);
        g_hb[row * HYP + h] = fmaxf(accb[r] + bb, 0.f);
    }
}

// ---------------------------------------------------------------------------
// Kernel 2: fused output.
// out[b,o] = sum_h hg[b,h] * (sum_i W2g[h,o,i]*x[b,i])   (phase C, dominant)
//          + sum_i b2g[o,i]*x[b,i]                        (phase A)
//          + sum_h hb[b,h]*W2b[h,o]                       (phase B)
//          + b2b[o]                                       (epilogue)
// Tile: BM=128 (batch) x BN=64 (out). 256 threads, 8x4 register tile.
// Phase C synthesizes A-tile = hg[b,h] * x[b,i] at smem-fill time, so all
// phases accumulate into one register tile.
// ---------------------------------------------------------------------------
#define BM 128
#define BN 64
#define KC 32
#define AS 132   // aT row stride (pad: float4-aligned, <=2-way store conflicts)
#define BS 68    // bT row stride

__global__ __launch_bounds__(256) void main_kernel(
    const float* __restrict__ x,
    const float* __restrict__ W2g, const float* __restrict__ b2g,
    const float* __restrict__ W2b, const float* __restrict__ b2b,
    float* __restrict__ out)
{
    __shared__ __align__(16) float aT[KC * AS];  // [k][b]
    __shared__ __align__(16) float bT[KC * BS];  // [k][o]

    const int b0  = blockIdx.x * BM;
    const int o0  = blockIdx.y * BN;
    const int tid = threadIdx.x;
    const int tx  = tid & 15;   // out dim, 4 cols each
    const int ty  = tid >> 4;   // batch dim, 8 rows each

    // aT fill mapping: thread -> (row bb, 16-wide k half)
    const int a_bb = tid >> 1;
    const int a_kh = tid & 1;
    // bT K-major fill mapping: thread -> (col oo, 8-wide k quarter)
    const int bk_oo = tid >> 2;
    const int bk_kq = tid & 3;

    float acc[8][4];
#pragma unroll
    for (int r = 0; r < 8; r++)
#pragma unroll
        for (int c = 0; c < 4; c++) acc[r][c] = 0.f;

    // A-tile: transpose-store 16 consecutive K elements of one row, scaled by s
    auto fillA = [&](const float* src, int ld, float s) {
        const float* p = src + a_bb * ld + a_kh * 16;
#pragma unroll
        for (int j = 0; j < 4; j++) {
            float4 v = *(const float4*)(p + j * 4);
            int kk = a_kh * 16 + j * 4;
            aT[(kk + 0) * AS + a_bb] = v.x * s;
            aT[(kk + 1) * AS + a_bb] = v.y * s;
            aT[(kk + 2) * AS + a_bb] = v.z * s;
            aT[(kk + 3) * AS + a_bb] = v.w * s;
        }
    };
    // B-tile from K-major source (rows indexed by o, K contiguous): transpose
    auto fillB_k = [&](const float* src, int ld) {
        const float* p = src + bk_oo * ld + bk_kq * 8;
#pragma unroll
        for (int j = 0; j < 2; j++) {
            float4 v = *(const float4*)(p + j * 4);
            int kk = bk_kq * 8 + j * 4;
            bT[(kk + 0) * BS + bk_oo] = v.x;
            bT[(kk + 1) * BS + bk_oo] = v.y;
            bT[(kk + 2) * BS + bk_oo] = v.z;
            bT[(kk + 3) * BS + bk_oo] = v.w;
        }
    };
    // B-tile from N-major source (rows indexed by k, o contiguous): direct copy
    auto fillB_n = [&](const float* src, int ld) {
#pragma unroll
        for (int j = 0; j < 2; j++) {
            int c  = j * 256 + tid;
            int kk = c >> 4;
            int og = c & 15;
            *(float4*)&bT[kk * BS + og * 4] = *(const float4*)(src + kk * ld + og * 4);
        }
    };
    auto mma = [&]() {
#pragma unroll 8
        for (int kk = 0; kk < KC; kk++) {
            float4 bf = *(const float4*)&bT[kk * BS + tx * 4];
            float4 a0 = *(const float4*)&aT[kk * AS + ty * 8];
            float4 a1 = *(const float4*)&aT[kk * AS + ty * 8 + 4];
            float ar[8] = {a0.x, a0.y, a0.z, a0.w, a1.x, a1.y, a1.z, a1.w};
            float br[4] = {bf.x, bf.y, bf.z, bf.w};
#pragma unroll
            for (int r = 0; r < 8; r++)
#pragma unroll
                for (int c = 0; c < 4; c++)
                    acc[r][c] = fmaf(ar[r], br[c], acc[r][c]);
        }
    };

    // ---- Phase A: + x @ b2g^T   (b2g viewed [OUT_F, IN_F], K-major) ----
#pragma unroll 1
    for (int i0 = 0; i0 < IN_F; i0 += KC) {
        fillA(x + (size_t)b0 * IN_F + i0, IN_F, 1.f);
        fillB_k(b2g + (size_t)o0 * IN_F + i0, IN_F);
        __syncthreads();
        mma();
        __syncthreads();
    }

    // ---- Phase B: + hb @ W2b   (W2b [HYP, OUT_F], N-major) ----
#pragma unroll 1
    for (int i0 = 0; i0 < HYP; i0 += KC) {
        fillA(g_hb + (size_t)b0 * HYP + i0, HYP, 1.f);
        fillB_n(W2b + (size_t)i0 * OUT_F + o0, OUT_F);
        __syncthreads();
        mma();
        __syncthreads();
    }

    // ---- Phase C: + sum_h diag(hg[:,h]) * (x @ W2g[h]^T)  (dominant) ----
#pragma unroll 1
    for (int h = 0; h < HYP; h++) {
        float s = g_hg[(size_t)(b0 + a_bb) * HYP + h];
        const float* Wh = W2g + (size_t)h * (OUT_F * IN_F) + (size_t)o0 * IN_F;
#pragma unroll 1
        for (int i0 = 0; i0 < IN_F; i0 += KC) {
            fillA(x + (size_t)b0 * IN_F + i0, IN_F, s);
            fillB_k(Wh + i0, IN_F);
            __syncthreads();
            mma();
            __syncthreads();
        }
    }

    // ---- Epilogue: + b2b, store ----
    float4 bbias = *(const float4*)(b2b + o0 + tx * 4);
#pragma unroll
    for (int r = 0; r < 8; r++) {
        int row = b0 + ty * 8 + r;
        float4 v;
        v.x = acc[r][0] + bbias.x;
        v.y = acc[r][1] + bbias.y;
        v.z = acc[r][2] + bbias.z;
        v.w = acc[r][3] + bbias.w;
        *(float4*)(out + (size_t)row * OUT_F + o0 + tx * 4) = v;
    }
}

// ---------------------------------------------------------------------------
extern "C" void kernel_launch(void* const* d_in, const int* in_sizes, int n_in,
                              void* d_out, int out_size)
{
    const float* x   = (const float*)d_in[0];
    const float* W1g = (const float*)d_in[1];
    const float* b1g = (const float*)d_in[2];
    const float* W2g = (const float*)d_in[3];
    const float* b2g = (const float*)d_in[4];
    const float* W1b = (const float*)d_in[5];
    const float* b1b = (const float*)d_in[6];
    const float* W2b = (const float*)d_in[7];
    const float* b2b = (const float*)d_in[8];
    float* out = (float*)d_out;

    hidden_kernel<<<B_SZ / 16, 256>>>(x, W1g, b1g, W1b, b1b);

    dim3 grid(B_SZ / BM, OUT_F / BN);
    main_kernel<<<grid, 256>>>(x, W2g, b2g, W2b, b2b, out);
}

// round 5
// speedup vs baseline: 8.7369x; 8.7369x over previous
#include <cuda_runtime.h>
#include <cuda_fp16.h>
#include <cstdint>

#define B_SZ  4096
#define IN_F  256
#define OUT_F 256
#define HYP   128
#define BM    128
#define BN    64

// ---------------- device scratch (allocation-free rule) ----------------
__device__ __align__(256) float  g_hgT[HYP * B_SZ];                    // [h][b] fp32
__device__ __align__(256) __half g_hb16[B_SZ * HYP];                   // [b][h]
__device__ __align__(256) __half g_x16[B_SZ * IN_F];                   // [b][i]
__device__ __align__(256) __half g_w2g16[(size_t)HYP * OUT_F * IN_F];  // [h][o][i]
__device__ __align__(256) __half g_b2g16[OUT_F * IN_F];                // [o][i]
__device__ __align__(256) __half g_w2bT16[OUT_F * HYP];                // [o][k]

// ---------------- PTX helpers (sm_80+ baseline ISA only) ----------------
__device__ __forceinline__ uint32_t smem_u32(const void* p) {
    uint32_t a;
    asm("{ .reg .u64 t; cvta.to.shared.u64 t, %1; cvt.u32.u64 %0, t; }" : "=r"(a) : "l"(p));
    return a;
}
#define CP16(dst, src) \
    asm volatile("cp.async.cg.shared.global [%0], [%1], 16;" :: "r"(dst), "l"(src) : "memory")
#define CP_COMMIT() asm volatile("cp.async.commit_group;" ::: "memory")
#define CP_WAIT(n)  asm volatile("cp.async.wait_group %0;" :: "n"(n) : "memory")

__device__ __forceinline__ void ldsm4(uint32_t* r, uint32_t addr) {
    asm volatile("ldmatrix.sync.aligned.m8n8.x4.shared.b16 {%0,%1,%2,%3}, [%4];"
        : "=r"(r[0]), "=r"(r[1]), "=r"(r[2]), "=r"(r[3]) : "r"(addr));
}
// in-place accumulate: d += A(16x16) * B(16x8)
__device__ __forceinline__ void mma_16816(float* d, const uint32_t* a, const uint32_t* b) {
    asm volatile(
        "mma.sync.aligned.m16n8k16.row.col.f32.f16.f16.f32 "
        "{%0,%1,%2,%3}, {%4,%5,%6,%7}, {%8,%9}, {%0,%1,%2,%3};"
        : "+f"(d[0]), "+f"(d[1]), "+f"(d[2]), "+f"(d[3])
        : "r"(a[0]), "r"(a[1]), "r"(a[2]), "r"(a[3]), "r"(b[0]), "r"(b[1]));
}

// ---------------- kernel 0: fp32 -> fp16 conversions ----------------
__global__ __launch_bounds__(256) void convert_kernel(
    const float* __restrict__ W2g, const float* __restrict__ b2g,
    const float* __restrict__ x,   const float* __restrict__ W2b)
{
    int64_t tid = (int64_t)blockIdx.x * blockDim.x + threadIdx.x;
    if (tid < OUT_F * HYP) {           // W2b transpose [k][o] -> [o][k]
        int o = (int)(tid >> 7), k = (int)(tid & 127);
        g_w2bT16[tid] = __float2half_rn(W2b[k * OUT_F + o]);
    }
    const int64_t N1 = (int64_t)HYP * OUT_F * IN_F / 4;
    const int64_t N2 = N1 + (int64_t)OUT_F * IN_F / 4;
    const int64_t N3 = N2 + (int64_t)B_SZ * IN_F / 4;
    int64_t stride = (int64_t)gridDim.x * blockDim.x;
    for (int64_t i = tid; i < N3; i += stride) {
        const float4* src; __half* dst; int64_t j;
        if (i < N1)      { src = (const float4*)W2g; dst = g_w2g16; j = i; }
        else if (i < N2) { src = (const float4*)b2g; dst = g_b2g16; j = i - N1; }
        else             { src = (const float4*)x;   dst = g_x16;   j = i - N2; }
        float4 v = src[j];
        __half2* d2 = (__half2*)(dst + j * 4);
        d2[0] = __floats2half2_rn(v.x, v.y);
        d2[1] = __floats2half2_rn(v.z, v.w);
    }
}

// ---------------- kernel 1: hidden activations (fp32, exact) ----------------
__global__ __launch_bounds__(256) void hidden_kernel(
    const float* __restrict__ x,
    const float* __restrict__ W1g, const float* __restrict__ b1g,
    const float* __restrict__ W1b, const float* __restrict__ b1b)
{
    __shared__ __align__(16) float xs[16 * IN_F];
    const int b0 = blockIdx.x * 16;
    const int tid = threadIdx.x;
    const int h = tid & (HYP - 1);
    const int half = tid >> 7;

    for (int idx = tid; idx < 16 * IN_F / 4; idx += 256)
        ((float4*)xs)[idx] = ((const float4*)(x + (size_t)b0 * IN_F))[idx];
    __syncthreads();

    float accg[8], accb[8];
#pragma unroll
    for (int r = 0; r < 8; r++) { accg[r] = 0.f; accb[r] = 0.f; }
    for (int i = 0; i < IN_F; i++) {
        float wg = W1g[i * HYP + h];
        float wb = W1b[i * HYP + h];
#pragma unroll
        for (int r = 0; r < 8; r++) {
            float xv = xs[(half * 8 + r) * IN_F + i];
            accg[r] = fmaf(xv, wg, accg[r]);
            accb[r] = fmaf(xv, wb, accb[r]);
        }
    }
    float bg = b1g[h], bb = b1b[h];
#pragma unroll
    for (int r = 0; r < 8; r++) {
        int row = b0 + half * 8 + r;
        g_hgT[(size_t)h * B_SZ + row] = fmaxf(accg[r] + bg, 0.f);
        g_hb16[(size_t)row * HYP + h] = __float2half_rn(fmaxf(accb[r] + bb, 0.f));
    }
}

// ---------------- kernel 2: mma.sync main ----------------
// smem (dynamic, swizzled: chunk16B index k8 XOR (row&7); row stride 512B):
#define X_OFF   0         // X tile 128 x 512B = 64KB (chunks 0..31 used)
#define HB_OFF  65536     // hb tile 128 x 512B = 64KB (chunks 0..15 used)
#define B_OFF   131072    // B double buffer 2 x 64 x 512B = 64KB
#define S_OFF   196608    // hg scale double buffer 2 x 512B
#define SMEM_TOTAL 197632

__global__ __launch_bounds__(256, 1) void main_kernel(
    float* __restrict__ out, const float* __restrict__ b2b)
{
    extern __shared__ __align__(1024) char smem[];
    const uint32_t sb = smem_u32(smem);
    const int tid = threadIdx.x;
    const int lane = tid & 31;
    const int wid = tid >> 5;
    const int wm = wid & 3;      // warp M position (x32)
    const int wn = wid >> 2;     // warp N position (x32)
    const int b0 = blockIdx.x * BM;
    const int o0 = blockIdx.y * BN;

    // B-tile + scale prefetch for iteration hh into buffer hh&1
    auto issueB = [&](int hh) {
        if (hh <= 129) {
            uint32_t dbuf = sb + B_OFF + (uint32_t)(hh & 1) * 32768;
            const __half* src; int nsh;
            if (hh < 128)       { src = g_w2g16 + (size_t)hh * OUT_F * IN_F + (size_t)o0 * IN_F; nsh = 5; }
            else if (hh == 128) { src = g_b2g16 + (size_t)o0 * IN_F; nsh = 5; }
            else                { src = g_w2bT16 + (size_t)o0 * HYP; nsh = 4; }
            int ldh = 1 << (nsh + 3);           // halves per row
            int msk = (1 << nsh) - 1;
            int tot = 64 << nsh;
            for (int idx = tid; idx < tot; idx += 256) {
                int row = idx >> nsh, k8 = idx & msk;
                CP16(dbuf + row * 512 + (uint32_t)((k8 ^ (row & 7)) << 4),
                     src + (size_t)row * ldh + k8 * 8);
            }
            if (hh < 128 && tid < 32)
                CP16(sb + S_OFF + (uint32_t)(hh & 1) * 512 + tid * 16,
                     g_hgT + (size_t)hh * B_SZ + b0 + tid * 4);
        }
        CP_COMMIT();
    };

    // ---- prologue: group0 = X + HB + B0 + S0; group1 = B1 + S1 ----
    for (int idx = tid; idx < 128 * 32; idx += 256) {
        int row = idx >> 5, k8 = idx & 31;
        CP16(sb + X_OFF + row * 512 + (uint32_t)((k8 ^ (row & 7)) << 4),
             g_x16 + (size_t)(b0 + row) * IN_F + k8 * 8);
    }
    for (int idx = tid; idx < 128 * 16; idx += 256) {
        int row = idx >> 4, k8 = idx & 15;
        CP16(sb + HB_OFF + row * 512 + (uint32_t)((k8 ^ (row & 7)) << 4),
             g_hb16 + (size_t)(b0 + row) * HYP + k8 * 8);
    }
    issueB(0);
    issueB(1);

    // ---- per-thread fragment addressing (precomputed) ----
    const uint32_t a_off0 = (uint32_t)(wm * 32 + (lane & 15)) * 512;  // mf=0; mf=1: +16*512
    const uint32_t a_sw   = (uint32_t)(lane & 7);
    const uint32_t a_hi   = (uint32_t)(lane >> 4);
    uint32_t b_off[4];
#pragma unroll
    for (int nn = 0; nn < 4; nn++)
        b_off[nn] = (uint32_t)(wn * 32 + nn * 8 + (lane & 7)) * 512;
    const uint32_t b_sw = (uint32_t)(lane & 7);
    const uint32_t b_hi = (uint32_t)(lane >> 3);

    float c[2][4][4];
#pragma unroll
    for (int mf = 0; mf < 2; mf++)
#pragma unroll
        for (int nn = 0; nn < 4; nn++)
#pragma unroll
            for (int e = 0; e < 4; e++) c[mf][nn][e] = 0.f;

    float p[2][4][4];

    auto do_k32 = [&](uint32_t abase, uint32_t bbase, int k32) {
        uint32_t Af[2][2][4];
#pragma unroll
        for (int mf = 0; mf < 2; mf++)
#pragma unroll
            for (int kr = 0; kr < 2; kr++) {
                uint32_t k8 = (uint32_t)(k32 * 4 + kr * 2) + a_hi;
                ldsm4(Af[mf][kr], abase + a_off0 + (uint32_t)mf * 8192 + ((k8 ^ a_sw) << 4));
            }
        uint32_t Bf[4][4];
#pragma unroll
        for (int nn = 0; nn < 4; nn++) {
            uint32_t k8 = (uint32_t)(k32 * 4) + b_hi;
            ldsm4(Bf[nn], bbase + b_off[nn] + ((k8 ^ b_sw) << 4));
        }
#pragma unroll
        for (int mf = 0; mf < 2; mf++)
#pragma unroll
            for (int nn = 0; nn < 4; nn++) {
                mma_16816(p[mf][nn], Af[mf][0], &Bf[nn][0]);
                mma_16816(p[mf][nn], Af[mf][1], &Bf[nn][2]);
            }
    };

    const uint32_t xb  = sb + X_OFF;
    const uint32_t hbb = sb + HB_OFF;

    // ---- mainloop: h<128: W2g[h] (scale hg); 128: b2g (s=1); 129: hb@W2bT (s=1) ----
    for (int h = 0; h <= 129; h++) {
        if (h >= 128) { CP_WAIT(0); } else { CP_WAIT(1); }
        __syncthreads();

#pragma unroll
        for (int mf = 0; mf < 2; mf++)
#pragma unroll
            for (int nn = 0; nn < 4; nn++)
#pragma unroll
                for (int e = 0; e < 4; e++) p[mf][nn][e] = 0.f;

        uint32_t bbase = sb + B_OFF + (uint32_t)(h & 1) * 32768;
        if (h != 129) {
#pragma unroll
            for (int k32 = 0; k32 < 8; k32++) do_k32(xb, bbase, k32);
        } else {
#pragma unroll
            for (int k32 = 0; k32 < 4; k32++) do_k32(hbb, bbase, k32);
        }

        // epilogue: C += s * P (s per-row fp32; 1.0 for h>=128)
        float s[2][2];
        if (h < 128) {
            const float* ss = (const float*)(smem + S_OFF + (size_t)(h & 1) * 512);
#pragma unroll
            for (int mf = 0; mf < 2; mf++)
#pragma unroll
                for (int g = 0; g < 2; g++)
                    s[mf][g] = ss[wm * 32 + mf * 16 + g * 8 + (lane >> 2)];
        } else {
            s[0][0] = s[0][1] = s[1][0] = s[1][1] = 1.f;
        }
#pragma unroll
        for (int mf = 0; mf < 2; mf++)
#pragma unroll
            for (int nn = 0; nn < 4; nn++)
#pragma unroll
                for (int e = 0; e < 4; e++)
                    c[mf][nn][e] = fmaf(s[mf][e >> 1], p[mf][nn][e], c[mf][nn][e]);

        __syncthreads();     // all warps done with buffer (h&1) before refill
        issueB(h + 2);
    }

    // ---- store: out = C + b2b ----
    const int r_base = b0 + wm * 32 + (lane >> 2);
    const int c_base = o0 + wn * 32 + (lane & 3) * 2;
#pragma unroll
    for (int mf = 0; mf < 2; mf++)
#pragma unroll
        for (int nn = 0; nn < 4; nn++) {
            float2 bb2 = *(const float2*)(b2b + c_base + nn * 8);
#pragma unroll
            for (int g = 0; g < 2; g++) {
                int row = r_base + mf * 16 + g * 8;
                float2 v;
                v.x = c[mf][nn][g * 2 + 0] + bb2.x;
                v.y = c[mf][nn][g * 2 + 1] + bb2.y;
                *(float2*)(out + (size_t)row * OUT_F + c_base + nn * 8) = v;
            }
        }
}

// ---------------- launch ----------------
extern "C" void kernel_launch(void* const* d_in, const int* in_sizes, int n_in,
                              void* d_out, int out_size)
{
    const float* x   = (const float*)d_in[0];
    const float* W1g = (const float*)d_in[1];
    const float* b1g = (const float*)d_in[2];
    const float* W2g = (const float*)d_in[3];
    const float* b2g = (const float*)d_in[4];
    const float* W1b = (const float*)d_in[5];
    const float* b1b = (const float*)d_in[6];
    const float* W2b = (const float*)d_in[7];
    const float* b2b = (const float*)d_in[8];
    float* out = (float*)d_out;

    cudaFuncSetAttribute(main_kernel, cudaFuncAttributeMaxDynamicSharedMemorySize, SMEM_TOTAL);

    convert_kernel<<<1024, 256>>>(W2g, b2g, x, W2b);
    hidden_kernel<<<B_SZ / 16, 256>>>(x, W1g, b1g, W1b, b1b);
    dim3 grid(B_SZ / BM, OUT_F / BN);
    main_kernel<<<grid, 256, SMEM_TOTAL>>>(out, b2b);
}

// round 7
// speedup vs baseline: 8.8257x; 1.0102x over previous
#include <cuda_runtime.h>
#include <cuda_fp16.h>
#include <cstdint>

#define B_SZ  4096
#define IN_F  256
#define OUT_F 256
#define HYP   128
#define BM    128
#define BN    64

// ---------------- device scratch (allocation-free rule) ----------------
__device__ __align__(256) float  g_hgT[HYP * B_SZ];                    // [h][b] fp32
__device__ __align__(256) __half g_hb16[B_SZ * HYP];                   // [b][h]
__device__ __align__(256) __half g_x16[B_SZ * IN_F];                   // [b][i]
__device__ __align__(256) __half g_w2g16[(size_t)HYP * OUT_F * IN_F];  // [h][o][i]
__device__ __align__(256) __half g_b2g16[OUT_F * IN_F];                // [o][i]
__device__ __align__(256) __half g_w2bT16[OUT_F * HYP];                // [o][k]

// ---------------- PTX helpers (sm_80+ baseline ISA only) ----------------
__device__ __forceinline__ uint32_t smem_u32(const void* p) {
    uint32_t a;
    asm("{ .reg .u64 t; cvta.to.shared.u64 t, %1; cvt.u32.u64 %0, t; }" : "=r"(a) : "l"(p));
    return a;
}
#define CP16(dst, src) \
    asm volatile("cp.async.cg.shared.global [%0], [%1], 16;" :: "r"(dst), "l"(src) : "memory")
#define CP_COMMIT() asm volatile("cp.async.commit_group;" ::: "memory")
#define CP_WAIT(n)  asm volatile("cp.async.wait_group %0;" :: "n"(n) : "memory")

__device__ __forceinline__ void ldsm4(uint32_t* r, uint32_t addr) {
    asm volatile("ldmatrix.sync.aligned.m8n8.x4.shared.b16 {%0,%1,%2,%3}, [%4];"
        : "=r"(r[0]), "=r"(r[1]), "=r"(r[2]), "=r"(r[3]) : "r"(addr));
}
// in-place accumulate: d += A(16x16) * B(16x8)
__device__ __forceinline__ void mma_16816(float* d, const uint32_t* a, const uint32_t* b) {
    asm volatile(
        "mma.sync.aligned.m16n8k16.row.col.f32.f16.f16.f32 "
        "{%0,%1,%2,%3}, {%4,%5,%6,%7}, {%8,%9}, {%0,%1,%2,%3};"
        : "+f"(d[0]), "+f"(d[1]), "+f"(d[2]), "+f"(d[3])
        : "r"(a[0]), "r"(a[1]), "r"(a[2]), "r"(a[3]), "r"(b[0]), "r"(b[1]));
}

// ---------------- kernel 0: prep = convert (blocks 256..1023) + hidden (blocks 0..255)
__global__ __launch_bounds__(256) void prep_kernel(
    const float* __restrict__ x,
    const float* __restrict__ W1g, const float* __restrict__ b1g,
    const float* __restrict__ W1b, const float* __restrict__ b1b,
    const float* __restrict__ W2g, const float* __restrict__ b2g,
    const float* __restrict__ W2b)
{
    if (blockIdx.x < 256) {
        // ---- hidden: hg/hb for 16 batch rows (fp32, exact) ----
        __shared__ __align__(16) float xs[16 * IN_F];
        const int b0 = blockIdx.x * 16;
        const int tid = threadIdx.x;
        const int h = tid & (HYP - 1);
        const int half = tid >> 7;

        for (int idx = tid; idx < 16 * IN_F / 4; idx += 256)
            ((float4*)xs)[idx] = ((const float4*)(x + (size_t)b0 * IN_F))[idx];
        __syncthreads();

        float accg[8], accb[8];
#pragma unroll
        for (int r = 0; r < 8; r++) { accg[r] = 0.f; accb[r] = 0.f; }
        for (int i = 0; i < IN_F; i++) {
            float wg = W1g[i * HYP + h];
            float wb = W1b[i * HYP + h];
#pragma unroll
            for (int r = 0; r < 8; r++) {
                float xv = xs[(half * 8 + r) * IN_F + i];
                accg[r] = fmaf(xv, wg, accg[r]);
                accb[r] = fmaf(xv, wb, accb[r]);
            }
        }
        float bg = b1g[h], bb = b1b[h];
#pragma unroll
        for (int r = 0; r < 8; r++) {
            int row = b0 + half * 8 + r;
            g_hgT[(size_t)h * B_SZ + row] = fmaxf(accg[r] + bg, 0.f);
            g_hb16[(size_t)row * HYP + h] = __float2half_rn(fmaxf(accb[r] + bb, 0.f));
        }
    } else {
        // ---- convert: fp32 -> fp16 ----
        int64_t tid = (int64_t)(blockIdx.x - 256) * 256 + threadIdx.x;
        if (tid < OUT_F * HYP) {           // W2b transpose [k][o] -> [o][k]
            int o = (int)(tid >> 7), k = (int)(tid & 127);
            g_w2bT16[tid] = __float2half_rn(W2b[k * OUT_F + o]);
        }
        const int64_t N1 = (int64_t)HYP * OUT_F * IN_F / 4;
        const int64_t N2 = N1 + (int64_t)OUT_F * IN_F / 4;
        const int64_t N3 = N2 + (int64_t)B_SZ * IN_F / 4;
        const int64_t stride = (int64_t)768 * 256;
        for (int64_t i = tid; i < N3; i += stride) {
            const float4* src; __half* dst; int64_t j;
            if (i < N1)      { src = (const float4*)W2g; dst = g_w2g16; j = i; }
            else if (i < N2) { src = (const float4*)b2g; dst = g_b2g16; j = i - N1; }
            else             { src = (const float4*)x;   dst = g_x16;   j = i - N2; }
            float4 v = src[j];
            __half2* d2 = (__half2*)(dst + j * 4);
            d2[0] = __floats2half2_rn(v.x, v.y);
            d2[1] = __floats2half2_rn(v.z, v.w);
        }
    }
}

// ---------------- kernel 1: mma.sync main ----------------
// smem: X 128x512B swizzled (64KB) | HB 128x256B swizzled (32KB)
//       B 3x 64x512B (96KB) | S 4x 512B scale buffers
#define X_OFF   0
#define HB_OFF  65536
#define B_OFF   98304
#define S_OFF   196608
#define SMEM_TOTAL 198656

__global__ __launch_bounds__(256, 1) void main_kernel(
    float* __restrict__ out, const float* __restrict__ b2b)
{
    extern __shared__ __align__(1024) char smem[];
    const uint32_t sb = smem_u32(smem);
    const int tid = threadIdx.x;
    const int lane = tid & 31;
    const int wid = tid >> 5;
    const int wm = wid & 3;      // warp M position (x32)
    const int wn = wid >> 2;     // warp N position (x32)
    const int b0 = blockIdx.x * BM;
    const int o0 = blockIdx.y * BN;

    // B-tile (buffer hh%3) + hg scale (buffer hh&3) prefetch; one commit group always
    auto issueB = [&](int hh) {
        if (hh <= 129) {
            uint32_t dbuf = sb + B_OFF + (uint32_t)(hh % 3) * 32768;
            const __half* src; int nsh;
            if (hh < 128)       { src = g_w2g16 + (size_t)hh * OUT_F * IN_F + (size_t)o0 * IN_F; nsh = 5; }
            else if (hh == 128) { src = g_b2g16 + (size_t)o0 * IN_F; nsh = 5; }
            else                { src = g_w2bT16 + (size_t)o0 * HYP; nsh = 4; }
            int ldh = 1 << (nsh + 3);
            int msk = (1 << nsh) - 1;
            int tot = 64 << nsh;
            for (int idx = tid; idx < tot; idx += 256) {
                int row = idx >> nsh, k8 = idx & msk;
                CP16(dbuf + row * 512 + (uint32_t)((k8 ^ (row & 7)) << 4),
                     src + (size_t)row * ldh + k8 * 8);
            }
            if (hh < 128 && tid < 32)
                CP16(sb + S_OFF + (uint32_t)(hh & 3) * 512 + tid * 16,
                     g_hgT + (size_t)hh * B_SZ + b0 + tid * 4);
        }
        CP_COMMIT();
    };

    // ---- prologue: g0 = X + HB; g1 = B0 + S0; g2 = B1 + S1 ----
    for (int idx = tid; idx < 128 * 32; idx += 256) {
        int row = idx >> 5, k8 = idx & 31;
        CP16(sb + X_OFF + row * 512 + (uint32_t)((k8 ^ (row & 7)) << 4),
             g_x16 + (size_t)(b0 + row) * IN_F + k8 * 8);
    }
    for (int idx = tid; idx < 128 * 16; idx += 256) {
        int row = idx >> 4, k8 = idx & 15;
        CP16(sb + HB_OFF + row * 256 + (uint32_t)((k8 ^ (row & 7)) << 4),
             g_hb16 + (size_t)(b0 + row) * HYP + k8 * 8);
    }
    CP_COMMIT();
    issueB(0);
    issueB(1);

    // ---- per-thread fragment addressing ----
    const uint32_t a_row = (uint32_t)(wm * 32 + (lane & 15));
    const uint32_t a_sw  = (uint32_t)(lane & 7);
    const uint32_t a_hi  = (uint32_t)(lane >> 4);
    uint32_t b_off[4];
#pragma unroll
    for (int nn = 0; nn < 4; nn++)
        b_off[nn] = (uint32_t)(wn * 32 + nn * 8 + (lane & 7)) * 512;
    const uint32_t b_sw = (uint32_t)(lane & 7);
    const uint32_t b_hi = (uint32_t)(lane >> 3);

    float c[2][4][4];
    float p0[2][4][4], p1[2][4][4];
#pragma unroll
    for (int mf = 0; mf < 2; mf++)
#pragma unroll
        for (int nn = 0; nn < 4; nn++)
#pragma unroll
            for (int e = 0; e < 4; e++) {
                c[mf][nn][e] = 0.f; p0[mf][nn][e] = 0.f; p1[mf][nn][e] = 0.f;
            }

    const uint32_t xb  = sb + X_OFF;
    const uint32_t hbb = sb + HB_OFF;

    // one k32 step: 8 LDSM.x4 + 16 MMA into pc
    auto do_k32 = [&](uint32_t abase, uint32_t rs, uint32_t bbase, int k32,
                      float (&pc)[2][4][4]) {
        uint32_t Af[2][2][4];
#pragma unroll
        for (int mf = 0; mf < 2; mf++)
#pragma unroll
            for (int kr = 0; kr < 2; kr++) {
                uint32_t k8 = (uint32_t)(k32 * 4 + kr * 2) + a_hi;
                ldsm4(Af[mf][kr], abase + (a_row + (uint32_t)mf * 16) * rs + ((k8 ^ a_sw) << 4));
            }
        uint32_t Bf[4][4];
#pragma unroll
        for (int nn = 0; nn < 4; nn++) {
            uint32_t k8 = (uint32_t)(k32 * 4) + b_hi;
            ldsm4(Bf[nn], bbase + b_off[nn] + ((k8 ^ b_sw) << 4));
        }
#pragma unroll
        for (int mf = 0; mf < 2; mf++)
#pragma unroll
            for (int nn = 0; nn < 4; nn++) {
                mma_16816(pc[mf][nn], Af[mf][0], &Bf[nn][0]);
                mma_16816(pc[mf][nn], Af[mf][1], &Bf[nn][2]);
            }
    };

    // epilogue tile (mf,nn) of previous iteration: c += s*pp, pp = 0
    auto epi_tile = [&](int mf, int nn, float (&pp)[2][4][4], const float* s2) {
#pragma unroll
        for (int e = 0; e < 4; e++) {
            c[mf][nn][e] = fmaf(s2[mf * 2 + (e >> 1)], pp[mf][nn][e], c[mf][nn][e]);
            pp[mf][nn][e] = 0.f;
        }
    };

    // one h-iteration: compute h into pc, interleave epilogue of h-1 from pp
    auto iter = [&](int h, float (&pc)[2][4][4], float (&pp)[2][4][4]) {
        CP_WAIT(1);
        __syncthreads();
        float s2[4] = {1.f, 1.f, 1.f, 1.f};
        if (h >= 1 && h <= 128) {
            const float* ss = (const float*)(smem + S_OFF + (size_t)((h - 1) & 3) * 512);
#pragma unroll
            for (int mf = 0; mf < 2; mf++)
#pragma unroll
                for (int g = 0; g < 2; g++)
                    s2[mf * 2 + g] = ss[wm * 32 + mf * 16 + g * 8 + (lane >> 2)];
        }
        issueB(h + 2);
        uint32_t bbase = sb + B_OFF + (uint32_t)(h % 3) * 32768;
        if (h != 129) {
#pragma unroll
            for (int k32 = 0; k32 < 8; k32++) {
                do_k32(xb, 512u, bbase, k32, pc);
                if (h > 0) epi_tile(k32 >> 2, k32 & 3, pp, s2);
            }
        } else {
#pragma unroll
            for (int k32 = 0; k32 < 4; k32++) {
                do_k32(hbb, 256u, bbase, k32, pc);
                epi_tile(0, k32, pp, s2);
                epi_tile(1, k32, pp, s2);
            }
        }
    };

    // ---- mainloop: h<128 W2g[h] (scaled); 128 b2g (s=1); 129 hb@W2bT (s=1) ----
#pragma unroll 1
    for (int h = 0; h < 130; h += 2) {
        iter(h,     p0, p1);
        iter(h + 1, p1, p0);
    }
    // tail: epilogue of h=129 (in p1), s = 1
#pragma unroll
    for (int mf = 0; mf < 2; mf++)
#pragma unroll
        for (int nn = 0; nn < 4; nn++)
#pragma unroll
            for (int e = 0; e < 4; e++)
                c[mf][nn][e] += p1[mf][nn][e];

    // ---- store: out = C + b2b ----
    const int r_base = b0 + wm * 32 + (lane >> 2);
    const int c_base = o0 + wn * 32 + (lane & 3) * 2;
#pragma unroll
    for (int mf = 0; mf < 2; mf++)
#pragma unroll
        for (int nn = 0; nn < 4; nn++) {
            float2 bb2 = *(const float2*)(b2b + c_base + nn * 8);
#pragma unroll
            for (int g = 0; g < 2; g++) {
                int row = r_base + mf * 16 + g * 8;
                float2 v;
                v.x = c[mf][nn][g * 2 + 0] + bb2.x;
                v.y = c[mf][nn][g * 2 + 1] + bb2.y;
                *(float2*)(out + (size_t)row * OUT_F + c_base + nn * 8) = v;
            }
        }
}

// ---------------- launch ----------------
extern "C" void kernel_launch(void* const* d_in, const int* in_sizes, int n_in,
                              void* d_out, int out_size)
{
    const float* x   = (const float*)d_in[0];
    const float* W1g = (const float*)d_in[1];
    const float* b1g = (const float*)d_in[2];
    const float* W2g = (const float*)d_in[3];
    const float* b2g = (const float*)d_in[4];
    const float* W1b = (const float*)d_in[5];
    const float* b1b = (const float*)d_in[6];
    const float* W2b = (const float*)d_in[7];
    const float* b2b = (const float*)d_in[8];
    float* out = (float*)d_out;

    cudaFuncSetAttribute(main_kernel, cudaFuncAttributeMaxDynamicSharedMemorySize, SMEM_TOTAL);

    prep_kernel<<<1024, 256>>>(x, W1g, b1g, W1b, b1b, W2g, b2g, W2b);
    dim3 grid(B_SZ / BM, OUT_F / BN);
    main_kernel<<<grid, 256, SMEM_TOTAL>>>(out, b2b);
}